// round 4
// baseline (speedup 1.0000x reference)
#include <cuda_runtime.h>
#include <cuda_bf16.h>
#include <math.h>

// Fixed problem shapes
constexpr int S  = 20;    // alphabet
constexpr int SS = S * S; // 400
constexpr int MM = 2;     // m
constexpr int KK = 2;     // k
constexpr int NB = 512;   // b
constexpr int LL = 512;   // L
constexpr int NRATES = 512;
constexpr int NT = 20;    // uniformization Taylor terms n = 0..19
constexpr int BPB = 4;    // b's per block in fused kernel

// Device scratch (allocations forbidden)
__device__ float g_C[MM * KK * NT * SS];  // C_n = M^n / n! per (m,k)
__device__ float g_mu[MM * KK];

__device__ __forceinline__ float softplusf(float x) {
    return fmaxf(x, 0.0f) + log1pf(expf(-fabsf(x)));
}

// ---------------------------------------------------------------------------
// Kernel A: per (m,k) build p (softmax), R, normalized Q, mu, and the 20
// uniformization coefficient matrices C_n = M^n/n!, M = Qnorm + mu*I >= 0.
// All reductions warp-parallel; only the 19-step power chain is serial.
// 4 blocks x 400 threads.
// ---------------------------------------------------------------------------
__global__ void setup_kernel(const float* __restrict__ exch,
                             const float* __restrict__ equi) {
    __shared__ float Qsh[SS], Msh[SS], Ca[SS], Cb[SS];
    __shared__ float psh[S], dsh[S];
    __shared__ float s_inv_mue, s_mu;

    const int mk  = blockIdx.x;
    const int tid = threadIdx.x;          // 0..399
    const int i = tid / S, j = tid - i * S;

    const float* E = exch + mk * SS;
    // R = softplus(0.5*(E + E^T)), zero diagonal
    float r = (i == j) ? 0.0f : softplusf(0.5f * (E[i * S + j] + E[j * S + i]));

    // warp 0: parallel softmax of equilibrium row (20 lanes active)
    if (tid < 32) {
        float q = (tid < S) ? equi[mk * S + tid] : -1e30f;
        float mx = q;
#pragma unroll
        for (int o = 16; o; o >>= 1) mx = fmaxf(mx, __shfl_xor_sync(~0u, mx, o));
        float e = (tid < S) ? expf(q - mx) : 0.0f;
        float sm = e;
#pragma unroll
        for (int o = 16; o; o >>= 1) sm += __shfl_xor_sync(~0u, sm, o);
        if (tid < S) psh[tid] = e / sm;
    }
    __syncthreads();

    const float qv = r * psh[j];          // off-diagonal Q entries (diag = 0)
    Qsh[tid] = qv;
    __syncthreads();

    if (j == 0) {                         // 20 parallel row sums
        float d = 0.0f;
#pragma unroll
        for (int t = 0; t < S; t++) d += Qsh[i * S + t];
        dsh[i] = d;
    }
    __syncthreads();

    // warp 0: mue = sum p_i * d_i ; mu = max_i d_i / mue
    if (tid < 32) {
        float pd = (tid < S) ? psh[tid] * dsh[tid] : 0.0f;
        float mue = pd;
#pragma unroll
        for (int o = 16; o; o >>= 1) mue += __shfl_xor_sync(~0u, mue, o);
        mue = fmaxf(mue, 1e-16f);
        const float inv = 1.0f / mue;
        float dm = (tid < S) ? dsh[tid] * inv : 0.0f;
#pragma unroll
        for (int o = 16; o; o >>= 1) dm = fmaxf(dm, __shfl_xor_sync(~0u, dm, o));
        if (tid == 0) { s_inv_mue = inv; s_mu = dm; g_mu[mk] = dm; }
    }
    __syncthreads();

    const float inv = s_inv_mue, mu = s_mu;
    // M = Q/mue + (mu - d_i/mue) on diagonal  (elementwise >= 0)
    Msh[tid] = qv * inv + ((i == j) ? (mu - dsh[i] * inv) : 0.0f);

    float c0 = (i == j) ? 1.0f : 0.0f;    // C_0 = I
    Ca[tid] = c0;
    g_C[(mk * NT + 0) * SS + tid] = c0;
    __syncthreads();

    float* cur = Ca;
    float* nxt = Cb;
    for (int n = 1; n < NT; n++) {
        float acc = 0.0f;
#pragma unroll
        for (int t = 0; t < S; t++) acc += cur[i * S + t] * Msh[t * S + j];
        acc *= (1.0f / (float)n);
        nxt[tid] = acc;
        g_C[(mk * NT + n) * SS + tid] = acc;
        __syncthreads();
        float* tmp = cur; cur = nxt; nxt = tmp;
    }
}

// ---------------------------------------------------------------------------
// Kernel B (fused expm + gather): one block per 4 consecutive b's of one m.
// Thread tid<800 owns one (k, i, j) matrix entry with its 20 Taylor
// coefficients in registers. Per b: scalar tau -> Horner -> P in SMEM ->
// 5120 fully-coalesced float4 output stores. 256 blocks x 1024 threads,
// 2 blocks/SM.
// ---------------------------------------------------------------------------
__global__ void __launch_bounds__(1024, 2)
probs_kernel(const int* __restrict__ seq,
             const int* __restrict__ ridx,
             const float* __restrict__ tauk,
             float4* __restrict__ out4) {
    __shared__ float Psh[KK * SS];          // 800 floats: (k, row, col)
    __shared__ int   seqsh[BPB * LL];       // 2048 ints = 8 KB
    __shared__ float s_tau[BPB];            // tau per b
    __shared__ float s_scale[BPB * KK];     // exp(-tau*mu) per (b,k)

    const int grp = blockIdx.x;             // 0..255
    const int m   = grp >> 7;               // 128 groups per m
    const int b0  = (grp & 127) * BPB;
    const int tid = threadIdx.x;            // 0..1023

    // Sequences for the 4 b's: 512 int4 loads
    if (tid < (BPB * LL) / 4) {
        const int4* sq = (const int4*)(seq + (m * NB + b0) * LL);
        ((int4*)seqsh)[tid] = sq[tid];
    }

    // tau + per-(b,k) scale (first 8 lanes, race-free)
    if (tid < BPB * KK) {
        const int bb = tid >> 1, kk2 = tid & 1;
        const int rb = ridx[m * NB + b0 + bb];
        const float tau = softplusf(tauk[m * NRATES + rb]);
        if (kk2 == 0) s_tau[bb] = tau;
        s_scale[tid] = expf(-tau * g_mu[m * KK + kk2]);
    }

    // Register-resident coefficients: thread tid<800 owns entry (kk, e)
    const int kk  = tid / SS;               // 0 or 1 (masked for tid>=800)
    const int e   = tid - kk * SS;
    const bool act = tid < KK * SS;
    float c[NT];
    if (act) {
        const float* C = g_C + (m * KK + kk) * NT * SS;
#pragma unroll
        for (int n = 0; n < NT; n++) c[n] = __ldg(C + n * SS + e);
    }
    __syncthreads();

    const float4* P4 = (const float4*)Psh;
    for (int bb = 0; bb < BPB; bb++) {
        if (act) {
            const float tau = s_tau[bb];
            float a = c[NT - 1];
#pragma unroll
            for (int n = NT - 2; n >= 0; n--) a = fmaf(a, tau, c[n]);
            Psh[tid] = a * s_scale[bb * KK + kk];
        }
        __syncthreads();

        // out[m, b, l, k, :] = P[k, seq[l], :]; 5120 float4 per b, coalesced
        float4* ob = out4 + (size_t)(m * NB + b0 + bb) * (LL * KK * 5);
#pragma unroll
        for (int it = 0; it < 5; it++) {
            const int idx = it * 1024 + tid;        // 0..5119
            const int l   = idx / 10;
            const int rr  = idx - l * 10;
            const int k2  = rr / 5;
            const int s4  = rr - k2 * 5;
            const int row = seqsh[bb * LL + l];
            ob[idx] = P4[k2 * (SS / 4) + row * 5 + s4];
        }
        __syncthreads();                            // protect Psh before next b
    }
}

// ---------------------------------------------------------------------------
extern "C" void kernel_launch(void* const* d_in, const int* in_sizes, int n_in,
                              void* d_out, int out_size) {
    const int*   seq  = (const int*)d_in[0];    // (m,b,L) int32
    const int*   ridx = (const int*)d_in[1];    // (m,b) int32
    const float* tauk = (const float*)d_in[2];  // (m,num_rates) f32
    const float* exch = (const float*)d_in[3];  // (m,k,S,S) f32
    const float* equi = (const float*)d_in[4];  // (m,k,S) f32

    setup_kernel<<<MM * KK, SS>>>(exch, equi);
    probs_kernel<<<MM * (NB / BPB), 1024>>>(seq, ridx, tauk, (float4*)d_out);
}

// round 8
// speedup vs baseline: 1.2280x; 1.2280x over previous
#include <cuda_runtime.h>
#include <cuda_bf16.h>
#include <math.h>

// Fixed problem shapes
constexpr int S  = 20;    // alphabet
constexpr int SS = S * S; // 400
constexpr int MM = 2;     // m
constexpr int KK = 2;     // k
constexpr int NB = 512;   // b
constexpr int LL = 512;   // L
constexpr int NRATES = 512;
constexpr int NT = 20;    // uniformization Taylor terms n = 0..19
constexpr int BPB = 4;    // b's per block in fused kernel

// Device scratch (allocations forbidden)
__device__ float g_C[MM * KK * NT * SS];  // C_n = M^n / n! per (m,k)
__device__ float g_mu[MM * KK];

__device__ __forceinline__ float softplusf(float x) {
    return fmaxf(x, 0.0f) + log1pf(expf(-fabsf(x)));
}

// ---------------------------------------------------------------------------
// Kernel A: per (m,k) build p (softmax), R, normalized Q, mu, and the 20
// uniformization coefficient matrices C_n = M^n/n!, M = Qnorm + mu*I >= 0.
// 4 blocks x 400 threads; reductions warp-parallel.
// ---------------------------------------------------------------------------
__global__ void setup_kernel(const float* __restrict__ exch,
                             const float* __restrict__ equi) {
    __shared__ float Qsh[SS], Msh[SS], Ca[SS], Cb[SS];
    __shared__ float psh[S], dsh[S];
    __shared__ float s_inv_mue, s_mu;

    const int mk  = blockIdx.x;
    const int tid = threadIdx.x;          // 0..399
    const int i = tid / S, j = tid - i * S;

    const float* E = exch + mk * SS;
    float r = (i == j) ? 0.0f : softplusf(0.5f * (E[i * S + j] + E[j * S + i]));

    if (tid < 32) {                        // softmax of equilibrium row
        float q = (tid < S) ? equi[mk * S + tid] : -1e30f;
        float mx = q;
#pragma unroll
        for (int o = 16; o; o >>= 1) mx = fmaxf(mx, __shfl_xor_sync(~0u, mx, o));
        float e = (tid < S) ? expf(q - mx) : 0.0f;
        float sm = e;
#pragma unroll
        for (int o = 16; o; o >>= 1) sm += __shfl_xor_sync(~0u, sm, o);
        if (tid < S) psh[tid] = e / sm;
    }
    __syncthreads();

    const float qv = r * psh[j];          // off-diagonal Q entries (diag 0)
    Qsh[tid] = qv;
    __syncthreads();

    if (j == 0) {                         // 20 parallel row sums
        float d = 0.0f;
#pragma unroll
        for (int t = 0; t < S; t++) d += Qsh[i * S + t];
        dsh[i] = d;
    }
    __syncthreads();

    if (tid < 32) {                       // mue = sum p_i d_i ; mu = max d_i/mue
        float pd = (tid < S) ? psh[tid] * dsh[tid] : 0.0f;
        float mue = pd;
#pragma unroll
        for (int o = 16; o; o >>= 1) mue += __shfl_xor_sync(~0u, mue, o);
        mue = fmaxf(mue, 1e-16f);
        const float inv = 1.0f / mue;
        float dm = (tid < S) ? dsh[tid] * inv : 0.0f;
#pragma unroll
        for (int o = 16; o; o >>= 1) dm = fmaxf(dm, __shfl_xor_sync(~0u, dm, o));
        if (tid == 0) { s_inv_mue = inv; s_mu = dm; g_mu[mk] = dm; }
    }
    __syncthreads();

    const float inv = s_inv_mue, mu = s_mu;
    Msh[tid] = qv * inv + ((i == j) ? (mu - dsh[i] * inv) : 0.0f);

    float c0 = (i == j) ? 1.0f : 0.0f;    // C_0 = I
    Ca[tid] = c0;
    g_C[(mk * NT + 0) * SS + tid] = c0;
    __syncthreads();

    float* cur = Ca;
    float* nxt = Cb;
    for (int n = 1; n < NT; n++) {
        float acc = 0.0f;
#pragma unroll
        for (int t = 0; t < S; t++) acc += cur[i * S + t] * Msh[t * S + j];
        acc *= (1.0f / (float)n);
        nxt[tid] = acc;
        g_C[(mk * NT + n) * SS + tid] = acc;
        __syncthreads();
        float* tmp = cur; cur = nxt; nxt = tmp;
    }
}

// ---------------------------------------------------------------------------
// Kernel B (fused expm + gather, two barriers total):
// Phase 1: load sequences + tau/scale.
// Phase 2: ALL 4 P matrices -> SMEM (Horner, coefficients in registers).
// Phase 3: one uninterrupted store stream — 20 fully-unrolled independent
//          LDS.128->STG.128 pairs per thread; 320 KB/block contiguous.
// 256 blocks x 1024 threads, 2 blocks/SM (thread cap).
// ---------------------------------------------------------------------------
__global__ void __launch_bounds__(1024, 2)
probs_kernel(const int* __restrict__ seq,
             const int* __restrict__ ridx,
             const float* __restrict__ tauk,
             float4* __restrict__ out4) {
    __shared__ float Psh[BPB * KK * SS];    // 3200 floats = 12.8 KB
    __shared__ int   seqsh[BPB * LL];       // 2048 ints = 8 KB
    __shared__ float s_tau[BPB];
    __shared__ float s_scale[BPB * KK];

    const int grp = blockIdx.x;             // 0..255
    const int m   = grp >> 7;               // 128 groups per m
    const int b0  = (grp & 127) * BPB;
    const int tid = threadIdx.x;            // 0..1023

    // ---- Phase 1: sequences (512 int4) + tau/scale (8 lanes) ----
    if (tid < (BPB * LL) / 4) {
        const int4* sq = (const int4*)(seq + (m * NB + b0) * LL);
        ((int4*)seqsh)[tid] = sq[tid];
    }
    if (tid < BPB * KK) {
        const int bb = tid >> 1, kk2 = tid & 1;
        const int rb = ridx[m * NB + b0 + bb];
        const float tau = softplusf(tauk[m * NRATES + rb]);
        if (kk2 == 0) s_tau[bb] = tau;
        s_scale[tid] = expf(-tau * g_mu[m * KK + kk2]);
    }

    // Coefficients in registers: thread tid<800 owns entry (kk, e)
    const int kk  = tid / SS;
    const int e   = tid - kk * SS;
    const bool act = tid < KK * SS;
    float c[NT];
    if (act) {
        const float* C = g_C + (m * KK + kk) * NT * SS;
#pragma unroll
        for (int n = 0; n < NT; n++) c[n] = __ldg(C + n * SS + e);
    }
    __syncthreads();

    // ---- Phase 2: all BPB Horner evaluations into SMEM ----
    if (act) {
#pragma unroll
        for (int bb = 0; bb < BPB; bb++) {
            const float tau = s_tau[bb];
            float a = c[NT - 1];
#pragma unroll
            for (int n = NT - 2; n >= 0; n--) a = fmaf(a, tau, c[n]);
            Psh[bb * (KK * SS) + tid] = a * s_scale[bb * KK + kk];
        }
    }
    __syncthreads();

    // ---- Phase 3: single uninterrupted store stream ----
    // out[m, b0+bb, l, k, :] = P[bb, k, seq[l], :]
    // 20 independent LDS+STG pairs per thread, fully unrolled.
    const float4* P4 = (const float4*)Psh;          // [bb*200 + k2*100 + row*5 + s4]
    float4* ob = out4 + (size_t)(m * NB + b0) * (LL * KK * 5);
#pragma unroll
    for (int bb = 0; bb < BPB; bb++) {
        const int sbase = bb * LL;
        const int pbase = bb * 200;
        const int obase = bb * 5120;
#pragma unroll
        for (int it = 0; it < 5; it++) {
            const int idx = it * 1024 + tid;        // 0..5119 within this b
            const int l   = idx / 10;
            const int rr  = idx - l * 10;
            const int k2  = rr / 5;
            const int s4  = rr - k2 * 5;
            const int row = seqsh[sbase + l];
            ob[obase + idx] = P4[pbase + k2 * 100 + row * 5 + s4];
        }
    }
}

// ---------------------------------------------------------------------------
extern "C" void kernel_launch(void* const* d_in, const int* in_sizes, int n_in,
                              void* d_out, int out_size) {
    const int*   seq  = (const int*)d_in[0];    // (m,b,L) int32
    const int*   ridx = (const int*)d_in[1];    // (m,b) int32
    const float* tauk = (const float*)d_in[2];  // (m,num_rates) f32
    const float* exch = (const float*)d_in[3];  // (m,k,S,S) f32
    const float* equi = (const float*)d_in[4];  // (m,k,S) f32

    setup_kernel<<<MM * KK, SS>>>(exch, equi);
    probs_kernel<<<MM * (NB / BPB), 1024>>>(seq, ridx, tauk, (float4*)d_out);
}